// round 16
// baseline (speedup 1.0000x reference)
#include <cuda_runtime.h>
#include <cstddef>

// KitNET_5257039970983 — R14: R12 verbatim (cp.async ping-pong staging,
// constant-bank folded weights, warp-local, unroll-1, 80-reg point) with the
// weight stream SPLIT across ports: even M-rows + BT from constant (LDC),
// odd M-rows from a per-block smem copy (broadcast LDS.128) — balancing the
// LDC floor (8/SMSP) against the idle smem crossbar.
// Output: head_out(B,10) then tails(B,10), fp32.

#define NTILES 10
#define CDIM   10
#define HDIM   7
#define FDIM   100
#define TPB    256
#define RPB    512
#define PSTR   11                 // u64 per pair-row (88B, conflict-free LDS.64)
#define SLICE_U64 (32*PSTR)       // 352 u64 = 2816 B per warp per buffer

typedef unsigned long long u64;

struct FoldData {
    ulonglong2 MT[500];   // [t][co][ci pair]  (m,m)-packed; odd rows also in gMTodd
    ulonglong2 BT[50];    // [t][co pair]
    ulonglong2 MH[50];    // [j][i pair]
    ulonglong2 BH[5];
    int perm[100];
    int tbase[10];
    int pad[2];
};

__device__   FoldData gF;
__constant__ FoldData cF;
__device__   ulonglong2 gMTodd[250];   // [t][cp][cc] = MT row (2cp+1)

__device__ __forceinline__ u64 fma2(u64 a, u64 b, u64 c) {
    u64 d;
    asm("fma.rn.f32x2 %0, %1, %2, %3;" : "=l"(d) : "l"(a), "l"(b), "l"(c));
    return d;
}
__device__ __forceinline__ u64 pack2(float x, float y) {
    u64 d;
    asm("mov.b64 %0, {%1, %2};" : "=l"(d) : "f"(x), "f"(y));
    return d;
}
__device__ __forceinline__ void unpack2(u64 a, float& x, float& y) {
    asm("mov.b64 {%0, %1}, %2;" : "=f"(x), "=f"(y) : "l"(a));
}
__device__ __forceinline__ unsigned smem_u32(const void* p) {
    unsigned a;
    asm("{ .reg .u64 t; cvta.to.shared.u64 t, %1; cvt.u32.u64 %0, t; }"
        : "=r"(a) : "l"(p));
    return a;
}
__device__ __forceinline__ void cp4(unsigned dst, const float* src) {
    asm volatile("cp.async.ca.shared.global [%0], [%1], 4;"
                 :: "r"(dst), "l"(src));
}
__device__ __forceinline__ void cp16(unsigned dst, const void* src) {
    asm volatile("cp.async.cg.shared.global [%0], [%1], 16;"
                 :: "r"(dst), "l"(src));
}
#define CP_COMMIT() asm volatile("cp.async.commit_group;" ::: "memory")
#define CP_WAIT(n)  asm volatile("cp.async.wait_group %0;" :: "n"(n) : "memory")

// ================= setup kernel: fold weights into gF (1 block) =================
__global__ void kitnet_setup(const float* __restrict__ Wt,
                             const float* __restrict__ hbt,
                             const float* __restrict__ vbt,
                             const float* __restrict__ Wh,
                             const float* __restrict__ hbh,
                             const float* __restrict__ vbh,
                             const int*   __restrict__ clusters)
{
    __shared__ float sW[700], sHB[70], sVB[100], sWH[70], sHBH[7], sVBH[10];
    const int tid = threadIdx.x;
    for (int i = tid; i < 700; i += TPB) sW[i]  = Wt[i];
    for (int i = tid; i < 70;  i += TPB) sHB[i] = hbt[i];
    for (int i = tid; i < 100; i += TPB) sVB[i] = vbt[i];
    for (int i = tid; i < 70;  i += TPB) sWH[i] = Wh[i];
    if (tid < HDIM)   sHBH[tid] = hbh[tid];
    if (tid < NTILES) sVBH[tid] = vbh[tid];
    __syncthreads();

    float2* MT2 = (float2*)gF.MT;
    float2* BT2 = (float2*)gF.BT;
    float2* MH2 = (float2*)gF.MH;
    float2* BH2 = (float2*)gF.BH;

    for (int i = tid; i < NTILES * CDIM * CDIM; i += TPB) {
        int t  = i / 100;
        int r  = i - t * 100;
        int co = r / 10;
        int ci = r - co * 10;
        float m = (ci == co) ? -1.0f : 0.0f;
        #pragma unroll
        for (int h = 0; h < HDIM; ++h)
            m += sW[t * 70 + h * 10 + ci] * sW[t * 70 + h * 10 + co];
        MT2[i] = make_float2(m, m);
    }
    for (int i = tid; i < NTILES * CDIM; i += TPB) {
        int t = i / 10, c = i - t * 10;
        float b = sVB[i];
        #pragma unroll
        for (int h = 0; h < HDIM; ++h)
            b += sHB[t * HDIM + h] * sW[t * 70 + h * 10 + c];
        BT2[i] = make_float2(b, b);
    }
    for (int i = tid; i < CDIM * CDIM; i += TPB) {
        int j = i / 10, ii = i - j * 10;
        float m = 0.0f;
        #pragma unroll
        for (int h = 0; h < HDIM; ++h)
            m += sWH[h * 10 + ii] * sWH[h * 10 + j];
        MH2[i] = make_float2(m, m);
    }
    if (tid < NTILES) {
        float b = sVBH[tid];
        #pragma unroll
        for (int h = 0; h < HDIM; ++h)
            b += sHBH[h] * sWH[h * 10 + tid];
        BH2[tid] = make_float2(b, b);
    }
    for (int i = tid; i < FDIM; i += TPB) gF.perm[i] = clusters[i];
    if (tid < NTILES) {
        const int* pp = clusters + tid * 10;
        int b0 = pp[0];
        bool ok = true;
        #pragma unroll
        for (int j = 1; j < 10; ++j) ok = ok && (pp[j] == b0 + j);
        gF.tbase[tid] = ok ? b0 : -1;
    }
    __syncthreads();     // gF.MT writes visible block-wide

    // odd-row copy for the smem port: gMTodd[t*25 + cp*5 + cc] = MT[t][2cp+1][cc]
    if (tid < 250) {
        int t  = tid / 25;
        int r  = tid - t * 25;
        int cp = r / 5;
        int cc = r - cp * 5;
        gMTodd[tid] = gF.MT[t * 50 + (2 * cp + 1) * 5 + cc];
    }
}

// ================= main kernel =================

// err = xc @ M_t + b_t ; even rows + bias via constant, odd rows via smem
__device__ __forceinline__ u64 compute_tile(const u64 xc[CDIM],
                                            const ulonglong2* __restrict__ sMT,
                                            int t)
{
    const int mb  = t * 50;
    const int bb0 = t * 5;
    const ulonglong2* sRow = sMT + t * 25;
    u64 sq = 0ull;
    #pragma unroll
    for (int cp = 0; cp < 5; ++cp) {
        ulonglong2 bb = cF.BT[bb0 + cp];
        u64 a0 = bb.x, a1 = bb.y;
        #pragma unroll
        for (int cc = 0; cc < 5; ++cc) {
            ulonglong2 w0 = cF.MT[mb + (2*cp) * 5 + cc];     // LDC port
            ulonglong2 w1 = sRow[cp * 5 + cc];               // smem port (broadcast)
            a0 = fma2(xc[2*cc],   w0.x, a0);
            a0 = fma2(xc[2*cc+1], w0.y, a0);
            a1 = fma2(xc[2*cc],   w1.x, a1);
            a1 = fma2(xc[2*cc+1], w1.y, a1);
        }
        sq = fma2(a0, a0, sq);
        sq = fma2(a1, a1, sq);
    }
    return sq;
}

__global__ void __launch_bounds__(TPB, 3) kitnet_main(
    const float* __restrict__ x,
    float* __restrict__ out,
    int B)
{
    __shared__ u64 xs[2][8 * SLICE_U64];       // 2 x 22528 B ping-pong
    __shared__ ulonglong2 sMT[250];            // 4000 B odd-row weights

    const int tid  = threadIdx.x;
    const int lane = tid & 31;
    const int wid  = tid >> 5;
    const int base = blockIdx.x * RPB;
    const int rowbase = base + wid * 32;
    const float* xg = x + (size_t)rowbase * FDIM;

    // ---- one-time: pull odd-row weights into smem ----
    if (tid < 250) cp16(smem_u32(sMT + tid), gMTodd + tid);
    CP_COMMIT();
    CP_WAIT(0);
    __syncthreads();

    u64* bufA = xs[0] + wid * SLICE_U64;
    u64* bufB = xs[1] + wid * SLICE_U64;
    const unsigned dbA = smem_u32(bufA);
    const unsigned dbB = smem_u32(bufB);

    // per-lane map: item i -> (p,h,j); emap = srcoff(17b) | dstoff<<17
    int emap[20];
    #pragma unroll
    for (int i = 0; i < 20; ++i) {
        int id  = 32*i + lane;                 // 0..639
        int p   = id / 20;
        int rem = id - 20*p;
        int h   = rem / 10;
        int j   = rem - 10*h;
        int row = rowbase + p + h*256;
        int roff = (row < B ? row : (B - 1)) - rowbase;   // clamp (dup reads ok)
        emap[i] = (roff * FDIM + j) | ((p*22 + 2*j + h) << 17);
    }

    auto stage_issue = [&](unsigned db, int t) {
        const int tb = cF.tbase[t];
        if (tb >= 0) {
            #pragma unroll
            for (int i = 0; i < 20; ++i) {
                int e = emap[i];
                cp4(db + (unsigned)(e >> 17) * 4u, xg + (e & 0x1FFFF) + tb);
            }
        } else {
            const int* pp = cF.perm + t * 10;
            #pragma unroll
            for (int i = 0; i < 20; ++i) {
                int id  = 32*i + lane;
                int p   = id / 20;
                int rem = id - 20*p;
                int h   = rem / 10;
                int j   = rem - 10*h;
                int e   = emap[i];
                int rbase = (e & 0x1FFFF) - j;
                cp4(db + (unsigned)(e >> 17) * 4u, xg + rbase + pp[j]);
            }
        }
        CP_COMMIT();
    };

    u64 tails[NTILES];

    stage_issue(dbA, 0);

    #pragma unroll 1
    for (int t = 0; t < NTILES; ++t) {
        if (t < NTILES - 1) {
            stage_issue((t & 1) ? dbA : dbB, t + 1);
            CP_WAIT(1);                        // tile t's group complete
        } else {
            CP_WAIT(0);
        }
        __syncwarp();                          // all lanes' copies visible

        const u64* xsw = ((t & 1) ? bufB : bufA) + lane * PSTR;
        u64 xc[CDIM];
        #pragma unroll
        for (int j = 0; j < CDIM; ++j) xc[j] = xsw[j];

        u64 sq = compute_tile(xc, sMT, t);
        float e0, e1;
        unpack2(sq, e0, e1);
        // 0.5*log(0.1*e) = 0.5*log(e) - 0.5*log(10)
        tails[t] = pack2(__fmaf_rn(0.5f, __logf(e0), -1.15129255f),
                         __fmaf_rn(0.5f, __logf(e1), -1.15129255f));

        __syncwarp();                          // WAR: readers done before next issue
    }

    // ---- head: head_out = tails @ MH^T + b_h (constant-bank weights) ----
    u64 ho[NTILES];
    #pragma unroll
    for (int jp = 0; jp < 5; ++jp) {
        ulonglong2 bb = cF.BH[jp];
        u64 a0 = bb.x, a1 = bb.y;
        #pragma unroll
        for (int tt = 0; tt < 5; ++tt) {
            ulonglong2 w0 = cF.MH[(2*jp)   * 5 + tt];
            ulonglong2 w1 = cF.MH[(2*jp+1) * 5 + tt];
            a0 = fma2(tails[2*tt],   w0.x, a0);
            a0 = fma2(tails[2*tt+1], w0.y, a0);
            a1 = fma2(tails[2*tt],   w1.x, a1);
            a1 = fma2(tails[2*tt+1], w1.y, a1);
        }
        ho[2*jp]   = a0;
        ho[2*jp+1] = a1;
    }

    // ---- warp-local output restage (buffer A): round 0 = head, 1 = tails ----
    float* slf = (float*)bufA;
    const long long B10 = (long long)B * NTILES;
    #pragma unroll 1
    for (int r = 0; r < 2; ++r) {
        const u64* src = r ? tails : ho;
        #pragma unroll
        for (int n = 0; n < NTILES; ++n) {
            float a, b;
            unpack2(src[n], a, b);
            slf[lane * 10 + n]       = a;      // rows rowbase..+32
            slf[320 + lane * 10 + n] = b;      // rows rowbase+256..+32
        }
        __syncwarp();
        const long long bound = (long long)(r + 1) * B10;
        #pragma unroll
        for (int i = 0; i < 5; ++i) {
            int q  = lane + 32 * i;            // 0..159 float4 index
            int h  = (q >= 80) ? 1 : 0;
            int qq = q - 80 * h;
            long long off = (long long)r * B10
                          + (long long)(rowbase + h * 256) * 10 + 4 * qq;
            float4 v = *(const float4*)(slf + h * 320 + 4 * qq);
            if (off + 4 <= bound) {
                *(float4*)(out + off) = v;
            } else {
                const float* vf = (const float*)&v;
                #pragma unroll
                for (int kk = 0; kk < 4; ++kk)
                    if (off + kk < bound) out[off + kk] = vf[kk];
            }
        }
        __syncwarp();
    }
}

extern "C" void kernel_launch(void* const* d_in, const int* in_sizes, int n_in,
                              void* d_out, int out_size)
{
    const float* x   = (const float*)d_in[0];
    const float* Wt  = (const float*)d_in[1];
    const float* hbt = (const float*)d_in[2];
    const float* vbt = (const float*)d_in[3];
    const float* Wh  = (const float*)d_in[4];
    const float* hbh = (const float*)d_in[5];
    const float* vbh = (const float*)d_in[6];
    const int*   cls = (const int*)d_in[7];

    const int B = in_sizes[0] / FDIM;
    const int grid = (B + RPB - 1) / RPB;

    kitnet_setup<<<1, TPB>>>(Wt, hbt, vbt, Wh, hbh, vbh, cls);

    void* gfp = nullptr;
    cudaGetSymbolAddress(&gfp, gF);
    cudaMemcpyToSymbolAsync(cF, gfp, sizeof(FoldData), 0,
                            cudaMemcpyDeviceToDevice, 0);

    kitnet_main<<<grid, TPB>>>(x, (float*)d_out, B);
}